// round 14
// baseline (speedup 1.0000x reference)
#include <cuda_runtime.h>
#include <cuda_fp16.h>
#include <math.h>
#include <cstdint>

#define NN   4096
#define KK   16
#define DIMM 256
#define RR   8192
#define GD   8

// ---- device scratch (static, no allocation) ----
__device__ int   g_hist[17];
__device__ int   g_off[17];
__device__ int   g_cnt[16];
__device__ int   g_done[16 * 8 * 32];          // [t][gd][mtile] ntile-completion counters
__device__ int   g_sorted_orig[NN];
__device__ int   g_sorted_len[NN];
__device__ float g_Wx[NN * 1024];
__device__ float g_C[GD][NN * DIMM];           // c state fp32
__device__ __half g_Yf16[2][NN * KK * DIMM];   // gate-0 seq outputs, layout (t*NN+s)
__device__ __half g_Hfin[GD][NN * DIMM];       // final h per gd (fp16)
__device__ float g_fseq[NN * KK * DIMM];       // fc0 projection, layout (t*NN+s)
__device__ float g_ydot[3 * NN * DIMM];        // fc1..3 projections of y_last
// fp16 h/H state + weights
__device__ __half g_hf16[RR * DIMM];            // h_tensor (rounded)
__device__ __half g_Hf16[2][GD][NN * DIMM];     // H state (double buffered)
__device__ __half g_xf16[NN * DIMM];            // x (rounded)
// packed weights: [gd][ntile8][chunk8] blocks of 128 n-rows x 64 k halves (K-major BT)
__device__ __half g_Bpf[8u * 8u * 8u * 8192u];
// packed fc weights: [gate4][256 n][512 k] fp16 (BT, K-major)
__device__ __half g_fcp[4u * 256u * 512u];
// packed W_w: [nt4][chunk4] blocks of 256 n-rows x 64 k halves
__device__ __half g_wwp[4u * 4u * 256u * 64u];

// ---- fast approx math (ex2/rcp approx, ~2^-22 error) ----
__device__ __forceinline__ float ex2f(float x) {
    float r; asm("ex2.approx.f32 %0, %1;" : "=f"(r) : "f"(x)); return r;
}
__device__ __forceinline__ float rcpf(float x) {
    float r; asm("rcp.approx.f32 %0, %1;" : "=f"(r) : "f"(x)); return r;
}
__device__ __forceinline__ float sigm(float x) {
    return rcpf(1.f + ex2f(-1.4426950408889634f * x));
}
__device__ __forceinline__ float tanh_fast(float x) {
    return 1.f - 2.f * rcpf(1.f + ex2f(2.8853900817779268f * x));
}

// ---- PTX helpers (non-'a' features only: cp.async, ldmatrix, mma.sync) ----
__device__ __forceinline__ uint32_t smem_u32(const void* p) {
    uint32_t a;
    asm("{ .reg .u64 t; cvta.to.shared.u64 t, %1; cvt.u32.u64 %0, t; }" : "=r"(a) : "l"(p));
    return a;
}
#define CP_ASYNC16(dst, src) \
    asm volatile("cp.async.cg.shared.global [%0], [%1], 16;" :: "r"(dst), "l"(src))
#define CP_COMMIT() asm volatile("cp.async.commit_group;" ::: "memory")
#define CP_WAIT(n)  asm volatile("cp.async.wait_group %0;" :: "n"(n) : "memory")

__device__ __forceinline__ void ldsm4(uint32_t* r, uint32_t addr) {
    asm volatile("ldmatrix.sync.aligned.m8n8.x4.shared.b16 {%0,%1,%2,%3}, [%4];"
                 : "=r"(r[0]), "=r"(r[1]), "=r"(r[2]), "=r"(r[3]) : "r"(addr));
}
__device__ __forceinline__ void mma_f16(float* c, const uint32_t* a, const uint32_t* b) {
    asm volatile("mma.sync.aligned.m16n8k16.row.col.f32.f16.f16.f32 "
                 "{%0,%1,%2,%3}, {%4,%5,%6,%7}, {%8,%9}, {%0,%1,%2,%3};"
                 : "+f"(c[0]), "+f"(c[1]), "+f"(c[2]), "+f"(c[3])
                 : "r"(a[0]), "r"(a[1]), "r"(a[2]), "r"(a[3]), "r"(b[0]), "r"(b[1]));
}

// ---------------- sorting by length (desc) ----------------
__global__ void zero_hist_kernel() { if (threadIdx.x < 17) g_hist[threadIdx.x] = 0; }

__global__ void len_hist_kernel(const int* __restrict__ indice) {
    int n = blockIdx.x * blockDim.x + threadIdx.x;
    if (n >= NN) return;
    int len = 0;
#pragma unroll
    for (int k = 0; k < KK; k++) len += (indice[n * KK + k] != -1);
    atomicAdd(&g_hist[len], 1);
}

__global__ void prefix_kernel() {
    if (threadIdx.x != 0 || blockIdx.x != 0) return;
    int run = 0;
    for (int l = 16; l >= 1; l--) { g_off[l] = run; run += g_hist[l]; }
    for (int t = 0; t < 16; t++) g_cnt[t] = g_off[t + 1] + g_hist[t + 1];
}

__global__ void scatter_kernel(const int* __restrict__ indice) {
    int n = blockIdx.x * blockDim.x + threadIdx.x;
    if (n >= NN) return;
    int len = 0;
#pragma unroll
    for (int k = 0; k < KK; k++) len += (indice[n * KK + k] != -1);
    int pos = atomicAdd(&g_off[len], 1);
    g_sorted_orig[pos] = n;
    g_sorted_len[pos]  = len;
}

// ------- prep: round h/x, pack weights (lstm + fc + wx), init states, zero flags -------
__global__ void prep_kernel(const float* __restrict__ ih, const float* __restrict__ ic,
                            const float* __restrict__ lk, const float* __restrict__ lr,
                            const float* __restrict__ h_tensor,
                            const float* __restrict__ fc_w,
                            const float* __restrict__ x, const float* __restrict__ W_w) {
    int idx = blockIdx.x * blockDim.x + threadIdx.x;
    if (idx < 16 * 8 * 32) {         // zero step-dependency flags (every call: graph replay)
        g_done[idx] = 0;
    }
    if (idx < RR * DIMM) {           // h_tensor round
        g_hf16[idx] = __float2half(h_tensor[idx]);
    }
    if (idx < NN * DIMM) {           // x round
        g_xf16[idx] = __float2half(x[idx]);
    }
    if (idx < 8 * 512 * 1024) {      // lstm weight pack: gate-interleaved, K-major BT blocks
        int gd = idx >> 19;
        int rem = idx & ((1 << 19) - 1);
        int kg = rem >> 10;          // 0..511
        int pc = rem & 1023;         // packed col: 4*j + q (q: 0=i,1=f,2=u,3=o)
        int oc = (pc & 3) * 256 + (pc >> 2);
        float w = (kg < 256) ? lk[((size_t)gd * 256 + kg) * 1024 + oc]
                             : lr[((size_t)gd * 256 + (kg - 256)) * 1024 + oc];
        int ntile = pc >> 7;         // 8 tiles of 128 packed cols
        int n     = pc & 127;
        int chunk = kg >> 6;
        int k     = kg & 63;
        size_t dst = ((size_t)(gd * 8 + ntile) * 8 + chunk) * 8192u + (size_t)n * 64 + k;
        g_Bpf[dst] = __float2half(w);
    }
    if (idx < 4 * 256 * 512) {       // fc weight pack: BT [gate][n][k]
        int g = idx >> 17;
        int rem = idx & ((1 << 17) - 1);
        int n = rem >> 9, k = rem & 511;
        g_fcp[idx] = __float2half(fc_w[((size_t)g * 512 + k) * 256 + n]);
    }
    if (idx < 4 * 4 * 256 * 64) {    // W_w pack: [nt][chunk][n][k]
        int k = idx & 63;
        int n = (idx >> 6) & 255;
        int chunk = (idx >> 14) & 3;
        int nt = idx >> 16;
        g_wwp[idx] = __float2half(W_w[((size_t)(chunk * 64 + k)) * 1024 + nt * 256 + n]);
    }
    if (idx < GD * NN * DIMM) {      // init H + C
        int j  = idx & (DIMM - 1);
        int gd = idx / (NN * DIMM);
        int r  = idx % (NN * DIMM);
        g_Hf16[0][gd][r] = __float2half(ih[gd * DIMM + j]);
        g_C[gd][r] = ic[gd * DIMM + j];
    }
}

// ---- HMMA recurrent steps: PERSISTENT t-looping chain CTAs with cross-step prefetch ----
// bid = (mtile*8 + gd)*8 + ntile. Group = 8 ntile CTAs; groups are independent chains.
#define SSPA      18432                    // A: 128 rows x 144B
#define SSPB      18432                    // B: 128 rows x 144B
#define SBUF      (SSPA + SSPB)            // 36864
#define SSM_CHILD (3 * SBUF)               // 110592 (2 x 128 ints)
#define SMEM_STEPK (3 * SBUF + 1024 + 128) // 111744

__global__ __launch_bounds__(256, 2) void step_mma_kernel(
    const int* __restrict__ indice, const float* __restrict__ lb) {
    extern __shared__ __align__(1024) char smem[];
    const int bid   = blockIdx.x;
    const int mtile = bid >> 6;
    const int gd    = (bid >> 3) & 7;
    const int ntile = bid & 7;
    const int m0    = mtile * 128;
    const int tid = threadIdx.x;
    const int wid = tid >> 5, lane = tid & 31;
    const uint32_t sb = smem_u32(smem);
    int* childs = (int*)(smem + SSM_CHILD);   // [2][128]

    const size_t bblk = (size_t)(gd * 8 + ntile) * 8;
    const int mw = wid & 3, nw = wid >> 2;    // 4 x 2 warp grid, warp 32x64
    const int m0w = mw * 32, n0w = nw * 64;
    const int am = lane >> 3, ar = lane & 7;
    const int dsel = gd & 1;
    const bool isG0 = gd < 2;

    // childs for t: computed into childs[t&1]
    auto calc_childs = [&](int tt) {
        if (tid < 128) {
            int s = m0 + tid;
            int ci = 0;
            if (tt < 16 && s < g_cnt[tt]) {
                int orig = g_sorted_orig[s];
                int len  = g_sorted_len[s];
                int tk = (gd & 1) ? (len - 1 - tt) : tt;
                ci = indice[orig * KK + tk];
            }
            childs[(tt & 1) * 128 + tid] = ci;
        }
    };

    // stage chunk c of step tt into buffer buf
    auto stageC = [&](int tt, int c, int buf) {
        uint32_t aS = sb + buf * SBUF;
        uint32_t bS = aS + SSPA;
        const __half* Hin = &g_Hf16[tt & 1][gd][0];
        const int* ch = &childs[(tt & 1) * 128];
#pragma unroll
        for (int i = 0; i < 4; i++) {       // A: 1024 segs of 16B
            int g = tid + i * 256;
            int row = g >> 3, seg = g & 7;
            const __half* src;
            if (c < 4) src = g_hf16 + (size_t)ch[row] * 256 + c * 64 + seg * 8;
            else       src = Hin + (size_t)(m0 + row) * 256 + (c - 4) * 64 + seg * 8;
            CP_ASYNC16(aS + row * 144 + seg * 16, src);
        }
        const __half* bw = g_Bpf + (bblk + c) * 8192u;
#pragma unroll
        for (int i = 0; i < 4; i++) {       // B: 1024 segs of 16B
            int g = tid + i * 256;
            int row = g >> 3, seg = g & 7;
            CP_ASYNC16(bS + row * 144 + seg * 16, bw + row * 64 + seg * 8);
        }
        CP_COMMIT();
    };

    calc_childs(0);
    __syncthreads();
    // prefetch slots 0,1 (t=0, chunks 0,1) -> buffers 0,1
    stageC(0, 0, 0);
    stageC(0, 1, 1);

    for (int t = 0; t < 16; t++) {
        if (m0 >= g_cnt[t]) { CP_WAIT(0); return; }
        const int Mact = g_cnt[t];

        float acc[2][8][4];
#pragma unroll
        for (int mt = 0; mt < 2; mt++)
#pragma unroll
            for (int nf = 0; nf < 8; nf++)
#pragma unroll
                for (int u = 0; u < 4; u++) acc[mt][nf][u] = 0.f;

        for (int c = 0; c < 8; c++) {
            CP_WAIT(1);
            __syncthreads();
            if (c == 2 && t > 0) {          // H(t-1) dependency gates staging chunk 4
                if (tid == 0) {
                    const int* flag = &g_done[(((t - 1) * 8 + gd) << 5) + mtile];
                    int v;
                    do {
                        asm volatile("ld.acquire.gpu.global.s32 %0, [%1];" : "=r"(v) : "l"(flag));
                    } while (v < 8);
                }
                __syncthreads();
            }
            // stage slot c+2 (chunk c+2 of t, or chunk c-6 of t+1)
            if (c + 2 < 8)      stageC(t, c + 2, (8 * t + c + 2) % 3);
            else if (t < 15)    stageC(t + 1, c - 6, (8 * t + c + 2) % 3);
            else                CP_COMMIT();   // keep group counting uniform
            if (c == 4) calc_childs(t + 1);    // childs for next step (read at c>=6 stages)
            // compute chunk c from buffer (8t+c)%3
            {
                uint32_t aS = sb + ((8 * t + c) % 3) * SBUF;
                uint32_t bS = aS + SSPA;
#pragma unroll
                for (int ks = 0; ks < 4; ks++) {
                    int k0 = ks * 16;
                    uint32_t af[2][4];
                    int arow_off = ((am & 1) ? 8 : 0) + ar;
                    int akk = (k0 + ((am >= 2) ? 8 : 0)) * 2;
#pragma unroll
                    for (int mt = 0; mt < 2; mt++) {
                        uint32_t off = (uint32_t)(m0w + mt * 16 + arow_off) * 144 + akk;
                        ldsm4(af[mt], aS + off);
                    }
                    int brow_off = ((am >= 2) ? 8 : 0) + ar;
                    int bkk = (k0 + ((am & 1) ? 8 : 0)) * 2;
#pragma unroll
                    for (int np = 0; np < 4; np++) {
                        uint32_t off = (uint32_t)(n0w + np * 16 + brow_off) * 144 + bkk;
                        uint32_t rb[4];
                        ldsm4(rb, bS + off);
                        uint32_t b0[2] = {rb[0], rb[1]}, b1[2] = {rb[2], rb[3]};
#pragma unroll
                        for (int mt = 0; mt < 2; mt++) {
                            mma_f16(acc[mt][np * 2], af[mt], b0);
                            mma_f16(acc[mt][np * 2 + 1], af[mt], b1);
                        }
                    }
                }
            }
        }
        __syncthreads();   // all compute(7) reads done before zs reuse

        // epilogue in 2 halves through the free buffer ((8t+7)%3); prefetched slots use the other two
        float* zs = (float*)(smem + ((8 * t + 7) % 3) * SBUF);   // [64][132]
        const int par = (t + 1) & 1;
        const int cntNext = (t < 15) ? g_cnt[t + 1] : 0;
#pragma unroll
        for (int h = 0; h < 2; h++) {
            int rbase = h * 64;
            if ((m0w >= rbase) && (m0w < rbase + 64)) {
#pragma unroll
                for (int mt = 0; mt < 2; mt++)
#pragma unroll
                    for (int nf = 0; nf < 8; nf++) {
                        int row = (m0w - rbase) + mt * 16 + (lane >> 2);
                        int col = n0w + nf * 8 + (lane & 3) * 2;
                        zs[row * 132 + col]           = acc[mt][nf][0];
                        zs[row * 132 + col + 1]       = acc[mt][nf][1];
                        zs[(row + 8) * 132 + col]     = acc[mt][nf][2];
                        zs[(row + 8) * 132 + col + 1] = acc[mt][nf][3];
                    }
            }
            __syncthreads();
#pragma unroll
            for (int i = 0; i < 8; i++) {
                int e = tid + i * 256;              // 64 rows x 32 dims
                int row = e >> 5, d = e & 31;
                int s = m0 + rbase + row;
                if (s < Mact) {
                    int jb = ntile * 32 + d;
                    float zi = zs[row * 132 + 4 * d + 0] + lb[gd * 1024 + jb];
                    float zf = zs[row * 132 + 4 * d + 1] + lb[gd * 1024 + 256 + jb];
                    float zu = zs[row * 132 + 4 * d + 2] + lb[gd * 1024 + 512 + jb];
                    float zo = zs[row * 132 + 4 * d + 3] + lb[gd * 1024 + 768 + jb];
                    size_t off = (size_t)s * DIMM + jb;
                    float cnew = sigm(zf) * g_C[gd][off] + sigm(zi) * tanh_fast(zu);
                    float hnew = sigm(zo) * tanh_fast(cnew);
                    g_C[gd][off] = cnew;
                    __half hh = __float2half(hnew);
                    g_Hf16[par][gd][off] = hh;
                    if (isG0) g_Yf16[dsel][((size_t)t * NN + s) * DIMM + jb] = hh;
                    if (s >= cntNext) g_Hfin[gd][off] = hh;
                }
            }
            __syncthreads();
        }

        // signal completion of (t, gd, mtile, ntile)
        __threadfence();
        __syncthreads();
        if (tid == 0) atomicAdd(&g_done[((t * 8 + gd) << 5) + mtile], 1);
    }
    CP_WAIT(0);
}

// ---- generic HMMA fc GEMM: C[M,256] = [A0|A1][M,512] @ Bp^T, 16 warps, 32x64 ----
#define SPA       18432                    // 128 rows x 144B
#define SPB       36864                    // 256 rows x 144B
#define BUF_B     (SPA + SPB)              // 55296
#define SMEM_FC   (3 * BUF_B + 512)        // 166400
#define NT        512

// mode 0: f_seq, grid (32, 16): y = t segment, prefix-trimmed by g_cnt[t].
// mode 9: y_last gates, grid (32, 3): gate = 1 + blockIdx.y
__global__ __launch_bounds__(NT, 1) void gemm_fc_kernel(int mode) {
    extern __shared__ __align__(1024) char smem[];
    const int tid = threadIdx.x;
    const int wid = tid >> 5, lane = tid & 31;
    const uint32_t sb = smem_u32(smem);

    int md = mode;
    if (md == 9) md = 1 + blockIdx.y;

    const __half *A0, *A1, *Bp;
    float* Cout;
    size_t rbase;                       // global row base for this CTA
    if (md == 0) {
        int tseg = blockIdx.y;
        int m0 = blockIdx.x * 128;
        if (m0 >= g_cnt[tseg]) return;  // prefix trim: only valid (t,s) rows
        rbase = (size_t)tseg * NN + m0;
        A0 = g_Yf16[0]; A1 = g_Yf16[1];
        Bp = g_fcp; Cout = g_fseq;
    } else {
        rbase = (size_t)blockIdx.x * 128;
        A0 = g_Hfin[2 * md]; A1 = g_Hfin[2 * md + 1];
        Bp = g_fcp + (size_t)md * 131072u;
        Cout = g_ydot + (size_t)(md - 1) * NN * DIMM;
    }

    float acc[2][8][4];
#pragma unroll
    for (int mt = 0; mt < 2; mt++)
#pragma unroll
        for (int nf = 0; nf < 8; nf++)
#pragma unroll
            for (int u = 0; u < 4; u++) acc[mt][nf][u] = 0.f;

    const int mw = wid & 3, nw = wid >> 2;
    const int m0w = mw * 32, n0w = nw * 64;
    const int am = lane >> 3, ar = lane & 7;

    auto stage = [&](int c) {
        uint32_t base = sb + (c % 3) * BUF_B;
        uint32_t aS = base;
        uint32_t bS = base + SPA;
#pragma unroll
        for (int i = 0; i < 2; i++) {
            int g = tid + i * NT;
            int row = g >> 3, seg = g & 7;
            const __half* src = (c < 4)
                ? A0 + (rbase + row) * 256 + c * 64 + seg * 8
                : A1 + (rbase + row) * 256 + (c - 4) * 64 + seg * 8;
            CP_ASYNC16(aS + row * 144 + seg * 16, src);
        }
#pragma unroll
        for (int i = 0; i < 4; i++) {
            int g = tid + i * NT;
            int row = g >> 3, seg = g & 7;   // row = n index, Bp stride 512
            CP_ASYNC16(bS + row * 144 + seg * 16, Bp + (size_t)row * 512 + c * 64 + seg * 8);
        }
        CP_COMMIT();
    };

    auto compute = [&](int c) {
        uint32_t base = sb + (c % 3) * BUF_B;
        uint32_t aS = base;
        uint32_t bS = base + SPA;
#pragma unroll
        for (int ks = 0; ks < 4; ks++) {
            int k0 = ks * 16;
            uint32_t af[2][4];
            int arow_off = ((am & 1) ? 8 : 0) + ar;
            int akk = (k0 + ((am >= 2) ? 8 : 0)) * 2;
#pragma unroll
            for (int mt = 0; mt < 2; mt++) {
                uint32_t off = (uint32_t)(m0w + mt * 16 + arow_off) * 144 + akk;
                ldsm4(af[mt], aS + off);
            }
            int brow_off = ((am >= 2) ? 8 : 0) + ar;
            int bkk = (k0 + ((am & 1) ? 8 : 0)) * 2;
#pragma unroll
            for (int np = 0; np < 4; np++) {
                uint32_t off = (uint32_t)(n0w + np * 16 + brow_off) * 144 + bkk;
                uint32_t rb[4];
                ldsm4(rb, bS + off);
                uint32_t b0[2] = {rb[0], rb[1]}, b1[2] = {rb[2], rb[3]};
#pragma unroll
                for (int mt = 0; mt < 2; mt++) {
                    mma_f16(acc[mt][np * 2], af[mt], b0);
                    mma_f16(acc[mt][np * 2 + 1], af[mt], b1);
                }
            }
        }
    };

    stage(0);
    stage(1);
#pragma unroll
    for (int c = 0; c < 8; c++) {
        if (c == 7) { CP_WAIT(0); } else { CP_WAIT(1); }
        __syncthreads();
        if (c + 2 < 8) stage(c + 2);
        compute(c);
    }
    __syncthreads();

    float* zs = (float*)smem;    // [128][264]
#pragma unroll
    for (int mt = 0; mt < 2; mt++)
#pragma unroll
        for (int nf = 0; nf < 8; nf++) {
            int row = m0w + mt * 16 + (lane >> 2);
            int col = n0w + nf * 8 + (lane & 3) * 2;
            zs[row * 264 + col]           = acc[mt][nf][0];
            zs[row * 264 + col + 1]       = acc[mt][nf][1];
            zs[(row + 8) * 264 + col]     = acc[mt][nf][2];
            zs[(row + 8) * 264 + col + 1] = acc[mt][nf][3];
        }
    __syncthreads();

#pragma unroll
    for (int i = 0; i < 16; i++) {          // 128 rows x 64 float4s
        int e = tid + i * NT;
        int row = e >> 6, q = e & 63;
        float4 v = make_float4(zs[row * 264 + q * 4], zs[row * 264 + q * 4 + 1],
                               zs[row * 264 + q * 4 + 2], zs[row * 264 + q * 4 + 3]);
        *(float4*)&Cout[(rbase + row) * 256 + q * 4] = v;
    }
}

// ---- Wx HMMA GEMM: Wx[4096,1024] = x_f16 @ W_w^T + W_b ; grid (32, 4), K=256 ----
__global__ __launch_bounds__(NT, 1) void wx_mma_kernel(const float* __restrict__ W_b) {
    extern __shared__ __align__(1024) char smem[];
    const int tid = threadIdx.x;
    const int wid = tid >> 5, lane = tid & 31;
    const uint32_t sb = smem_u32(smem);
    const int m0 = blockIdx.x * 128;
    const int nt = blockIdx.y;              // col tile of 256

    float acc[2][8][4];
#pragma unroll
    for (int mt = 0; mt < 2; mt++)
#pragma unroll
        for (int nf = 0; nf < 8; nf++)
#pragma unroll
            for (int u = 0; u < 4; u++) acc[mt][nf][u] = 0.f;

    const int mw = wid & 3, nw = wid >> 2;
    const int m0w = mw * 32, n0w = nw * 64;
    const int am = lane >> 3, ar = lane & 7;

    auto stage = [&](int c) {
        uint32_t base = sb + (c % 3) * BUF_B;
        uint32_t aS = base;
        uint32_t bS = base + SPA;
#pragma unroll
        for (int i = 0; i < 2; i++) {
            int g = tid + i * NT;
            int row = g >> 3, seg = g & 7;
            CP_ASYNC16(aS + row * 144 + seg * 16,
                       g_xf16 + (size_t)(m0 + row) * 256 + c * 64 + seg * 8);
        }
        const __half* bw = g_wwp + (size_t)(nt * 4 + c) * 16384u;
#pragma unroll
        for (int i = 0; i < 4; i++) {
            int g = tid + i * NT;
            int row = g >> 3, seg = g & 7;
            CP_ASYNC16(bS + row * 144 + seg * 16, bw + (size_t)row * 64 + seg * 8);
        }
        CP_COMMIT();
    };

    auto compute = [&](int c) {
        uint32_t base = sb + (c % 3) * BUF_B;
        uint32_t aS = base;
        uint32_t bS = base + SPA;
#pragma unroll
        for (int ks = 0; ks < 4; ks++) {
            int k0 = ks * 16;
            uint32_t af[2][4];
            int arow_off = ((am & 1) ? 8 : 0) + ar;
            int akk = (k0 + ((am >= 2) ? 8 : 0)) * 2;
#pragma unroll
            for (int mt = 0; mt < 2; mt++) {
                uint32_t off = (uint32_t)(m0w + mt * 16 + arow_off) * 144 + akk;
                ldsm4(af[mt], aS + off);
            }
            int brow_off = ((am >= 2) ? 8 : 0) + ar;
            int bkk = (k0 + ((am & 1) ? 8 : 0)) * 2;
#pragma unroll
            for (int np = 0; np < 4; np++) {
                uint32_t off = (uint32_t)(n0w + np * 16 + brow_off) * 144 + bkk;
                uint32_t rb[4];
                ldsm4(rb, bS + off);
                uint32_t b0[2] = {rb[0], rb[1]}, b1[2] = {rb[2], rb[3]};
#pragma unroll
                for (int mt = 0; mt < 2; mt++) {
                    mma_f16(acc[mt][np * 2], af[mt], b0);
                    mma_f16(acc[mt][np * 2 + 1], af[mt], b1);
                }
            }
        }
    };

    stage(0);
    stage(1);
#pragma unroll
    for (int c = 0; c < 4; c++) {
        if (c == 3) { CP_WAIT(0); } else { CP_WAIT(1); }
        __syncthreads();
        if (c + 2 < 4) stage(c + 2);
        compute(c);
    }
    __syncthreads();

    float* zs = (float*)smem;    // [128][264]
#pragma unroll
    for (int mt = 0; mt < 2; mt++)
#pragma unroll
        for (int nf = 0; nf < 8; nf++) {
            int row = m0w + mt * 16 + (lane >> 2);
            int col = n0w + nf * 8 + (lane & 3) * 2;
            zs[row * 264 + col]           = acc[mt][nf][0];
            zs[row * 264 + col + 1]       = acc[mt][nf][1];
            zs[(row + 8) * 264 + col]     = acc[mt][nf][2];
            zs[(row + 8) * 264 + col + 1] = acc[mt][nf][3];
        }
    __syncthreads();

#pragma unroll
    for (int i = 0; i < 16; i++) {          // 128 rows x 64 float4s
        int e = tid + i * NT;
        int row = e >> 6, q = e & 63;
        float4 b = *(const float4*)&W_b[nt * 256 + q * 4];
        float4 v = make_float4(zs[row * 264 + q * 4] + b.x, zs[row * 264 + q * 4 + 1] + b.y,
                               zs[row * 264 + q * 4 + 2] + b.z, zs[row * 264 + q * 4 + 3] + b.w);
        *(float4*)&g_Wx[(size_t)(m0 + row) * 1024 + nt * 256 + q * 4] = v;
    }
}

// ---------------- final combine (light) ----------------
__global__ __launch_bounds__(256) void combine_kernel(
    const float* __restrict__ c_tensor, const int* __restrict__ indice,
    float* __restrict__ out) {
    int s = blockIdx.x;
    int j = threadIdx.x;
    int orig = g_sorted_orig[s];
    int len  = g_sorted_len[s];

    __shared__ int ciS[KK];
    if (j < KK) ciS[j] = (j < len) ? indice[orig * KK + j] : 0;
    __syncthreads();

    float Wf = g_Wx[orig * 1024 + j];
    float bf = 0.f;
    for (int t = 0; t < len; t++) {
        float fs = g_fseq[((size_t)t * NN + s) * DIMM + j];
        bf += sigm(Wf + fs) * c_tensor[(size_t)ciS[t] * DIMM + j];
    }

    float d0 = g_ydot[(size_t)0 * NN * DIMM + (size_t)s * DIMM + j];
    float d1 = g_ydot[(size_t)1 * NN * DIMM + (size_t)s * DIMM + j];
    float d2 = g_ydot[(size_t)2 * NN * DIMM + (size_t)s * DIMM + j];

    float Wi = g_Wx[orig * 1024 + 256 + j];
    float Wu = g_Wx[orig * 1024 + 512 + j];
    float Wo = g_Wx[orig * 1024 + 768 + j];
    float bi = sigm(d0 + Wi);
    float bu = tanh_fast(d1 + Wu);
    float bo = sigm(d2 + Wo);
    float nc = bi * bu + bf;
    float nh = bo * tanh_fast(nc);
    out[(size_t)orig * DIMM + j] = nh;
    out[(size_t)NN * DIMM + (size_t)orig * DIMM + j] = nc;
}

// ---------------- launch ----------------
extern "C" void kernel_launch(void* const* d_in, const int* in_sizes, int n_in,
                              void* d_out, int out_size) {
    const float* x        = (const float*)d_in[0];
    const float* h_tensor = (const float*)d_in[1];
    const float* c_tensor = (const float*)d_in[2];
    const int*   indice   = (const int*)d_in[3];
    const float* W_w      = (const float*)d_in[4];
    const float* W_b      = (const float*)d_in[5];
    const float* lk       = (const float*)d_in[6];
    const float* lr       = (const float*)d_in[7];
    const float* lb       = (const float*)d_in[8];
    const float* ih       = (const float*)d_in[9];
    const float* ic       = (const float*)d_in[10];
    const float* fc       = (const float*)d_in[11];
    float* out = (float*)d_out;

    cudaFuncSetAttribute(step_mma_kernel, cudaFuncAttributeMaxDynamicSharedMemorySize,
                         SMEM_STEPK);
    cudaFuncSetAttribute(gemm_fc_kernel, cudaFuncAttributeMaxDynamicSharedMemorySize,
                         SMEM_FC);
    cudaFuncSetAttribute(wx_mma_kernel, cudaFuncAttributeMaxDynamicSharedMemorySize,
                         SMEM_FC);

    zero_hist_kernel<<<1, 32>>>();
    len_hist_kernel<<<NN / 256, 256>>>(indice);
    prefix_kernel<<<1, 1>>>();
    scatter_kernel<<<NN / 256, 256>>>(indice);
    prep_kernel<<<(GD * NN * DIMM) / 256, 256>>>(ih, ic, lk, lr, h_tensor, fc, x, W_w);
    step_mma_kernel<<<2048, 256, SMEM_STEPK>>>(indice, lb);   // persistent chains, all steps
    gemm_fc_kernel<<<dim3(32, 16), NT, SMEM_FC>>>(0);         // f_seq (prefix-trimmed)
    gemm_fc_kernel<<<dim3(32, 3), NT, SMEM_FC>>>(9);          // y_last gates 1..3
    wx_mma_kernel<<<dim3(32, 4), NT, SMEM_FC>>>(W_b);         // Wx (fp16 HMMA)
    combine_kernel<<<NN, 256>>>(c_tensor, indice, out);
}

// round 15
// speedup vs baseline: 1.1817x; 1.1817x over previous
#include <cuda_runtime.h>
#include <cuda_fp16.h>
#include <math.h>
#include <cstdint>

#define NN   4096
#define KK   16
#define DIMM 256
#define RR   8192
#define GD   8

// ---- device scratch (static, no allocation) ----
__device__ int   g_hist[17];
__device__ int   g_off[17];
__device__ int   g_cnt[16];
__device__ int   g_done[16 * 8 * 32];          // [t][gd][mtile] ntile-completion counters
__device__ int   g_sorted_orig[NN];
__device__ int   g_sorted_len[NN];
__device__ float g_Wx[NN * 1024];
__device__ float g_C[GD][NN * DIMM];           // c state fp32
__device__ __half g_Yf16[2][NN * KK * DIMM];   // gate-0 seq outputs, layout (t*NN+s)
__device__ __half g_Hfin[GD][NN * DIMM];       // final h per gd (fp16)
__device__ float g_fseq[NN * KK * DIMM];       // fc0 projection, layout (t*NN+s)
__device__ float g_ydot[3 * NN * DIMM];        // fc1..3 projections of y_last
// fp16 h/H state + weights
__device__ __half g_hf16[RR * DIMM];            // h_tensor (rounded)
__device__ __half g_Hf16[2][GD][NN * DIMM];     // H state (double buffered)
__device__ __half g_xf16[NN * DIMM];            // x (rounded)
// packed weights: [gd][ntile8][chunk8] blocks of 128 n-rows x 64 k halves (K-major BT)
__device__ __half g_Bpf[8u * 8u * 8u * 8192u];
// packed fc weights: [gate4][256 n][512 k] fp16 (BT, K-major)
__device__ __half g_fcp[4u * 256u * 512u];
// packed W_w: [nt4][chunk4] blocks of 256 n-rows x 64 k halves
__device__ __half g_wwp[4u * 4u * 256u * 64u];

// ---- fast approx math (ex2/rcp approx, ~2^-22 error) ----
__device__ __forceinline__ float ex2f(float x) {
    float r; asm("ex2.approx.f32 %0, %1;" : "=f"(r) : "f"(x)); return r;
}
__device__ __forceinline__ float rcpf(float x) {
    float r; asm("rcp.approx.f32 %0, %1;" : "=f"(r) : "f"(x)); return r;
}
__device__ __forceinline__ float sigm(float x) {
    return rcpf(1.f + ex2f(-1.4426950408889634f * x));
}
__device__ __forceinline__ float tanh_fast(float x) {
    return 1.f - 2.f * rcpf(1.f + ex2f(2.8853900817779268f * x));
}

// ---- PTX helpers (non-'a' features only: cp.async, ldmatrix, mma.sync) ----
__device__ __forceinline__ uint32_t smem_u32(const void* p) {
    uint32_t a;
    asm("{ .reg .u64 t; cvta.to.shared.u64 t, %1; cvt.u32.u64 %0, t; }" : "=r"(a) : "l"(p));
    return a;
}
#define CP_ASYNC16(dst, src) \
    asm volatile("cp.async.cg.shared.global [%0], [%1], 16;" :: "r"(dst), "l"(src))
#define CP_COMMIT() asm volatile("cp.async.commit_group;" ::: "memory")
#define CP_WAIT(n)  asm volatile("cp.async.wait_group %0;" :: "n"(n) : "memory")

__device__ __forceinline__ void ldsm4(uint32_t* r, uint32_t addr) {
    asm volatile("ldmatrix.sync.aligned.m8n8.x4.shared.b16 {%0,%1,%2,%3}, [%4];"
                 : "=r"(r[0]), "=r"(r[1]), "=r"(r[2]), "=r"(r[3]) : "r"(addr));
}
__device__ __forceinline__ void mma_f16(float* c, const uint32_t* a, const uint32_t* b) {
    asm volatile("mma.sync.aligned.m16n8k16.row.col.f32.f16.f16.f32 "
                 "{%0,%1,%2,%3}, {%4,%5,%6,%7}, {%8,%9}, {%0,%1,%2,%3};"
                 : "+f"(c[0]), "+f"(c[1]), "+f"(c[2]), "+f"(c[3])
                 : "r"(a[0]), "r"(a[1]), "r"(a[2]), "r"(a[3]), "r"(b[0]), "r"(b[1]));
}

// ---------------- sorting by length (desc) ----------------
__global__ void zero_hist_kernel() { if (threadIdx.x < 17) g_hist[threadIdx.x] = 0; }

__global__ void len_hist_kernel(const int* __restrict__ indice) {
    int n = blockIdx.x * blockDim.x + threadIdx.x;
    if (n >= NN) return;
    int len = 0;
#pragma unroll
    for (int k = 0; k < KK; k++) len += (indice[n * KK + k] != -1);
    atomicAdd(&g_hist[len], 1);
}

__global__ void prefix_kernel() {
    if (threadIdx.x != 0 || blockIdx.x != 0) return;
    int run = 0;
    for (int l = 16; l >= 1; l--) { g_off[l] = run; run += g_hist[l]; }
    for (int t = 0; t < 16; t++) g_cnt[t] = g_off[t + 1] + g_hist[t + 1];
}

__global__ void scatter_kernel(const int* __restrict__ indice) {
    int n = blockIdx.x * blockDim.x + threadIdx.x;
    if (n >= NN) return;
    int len = 0;
#pragma unroll
    for (int k = 0; k < KK; k++) len += (indice[n * KK + k] != -1);
    int pos = atomicAdd(&g_off[len], 1);
    g_sorted_orig[pos] = n;
    g_sorted_len[pos]  = len;
}

// ------- prep: round h/x, pack weights (lstm + fc + wx), init states, zero flags -------
__global__ void prep_kernel(const float* __restrict__ ih, const float* __restrict__ ic,
                            const float* __restrict__ lk, const float* __restrict__ lr,
                            const float* __restrict__ h_tensor,
                            const float* __restrict__ fc_w,
                            const float* __restrict__ x, const float* __restrict__ W_w) {
    int idx = blockIdx.x * blockDim.x + threadIdx.x;
    if (idx < 16 * 8 * 32) {         // zero step-dependency flags (every call: graph replay)
        g_done[idx] = 0;
    }
    if (idx < RR * DIMM) {           // h_tensor round
        g_hf16[idx] = __float2half(h_tensor[idx]);
    }
    if (idx < NN * DIMM) {           // x round
        g_xf16[idx] = __float2half(x[idx]);
    }
    if (idx < 8 * 512 * 1024) {      // lstm weight pack: gate-interleaved, K-major BT blocks
        int gd = idx >> 19;
        int rem = idx & ((1 << 19) - 1);
        int kg = rem >> 10;          // 0..511
        int pc = rem & 1023;         // packed col: 4*j + q (q: 0=i,1=f,2=u,3=o)
        int oc = (pc & 3) * 256 + (pc >> 2);
        float w = (kg < 256) ? lk[((size_t)gd * 256 + kg) * 1024 + oc]
                             : lr[((size_t)gd * 256 + (kg - 256)) * 1024 + oc];
        int ntile = pc >> 7;         // 8 tiles of 128 packed cols
        int n     = pc & 127;
        int chunk = kg >> 6;
        int k     = kg & 63;
        size_t dst = ((size_t)(gd * 8 + ntile) * 8 + chunk) * 8192u + (size_t)n * 64 + k;
        g_Bpf[dst] = __float2half(w);
    }
    if (idx < 4 * 256 * 512) {       // fc weight pack: BT [gate][n][k]
        int g = idx >> 17;
        int rem = idx & ((1 << 17) - 1);
        int n = rem >> 9, k = rem & 511;
        g_fcp[idx] = __float2half(fc_w[((size_t)g * 512 + k) * 256 + n]);
    }
    if (idx < 4 * 4 * 256 * 64) {    // W_w pack: [nt][chunk][n][k]
        int k = idx & 63;
        int n = (idx >> 6) & 255;
        int chunk = (idx >> 14) & 3;
        int nt = idx >> 16;
        g_wwp[idx] = __float2half(W_w[((size_t)(chunk * 64 + k)) * 1024 + nt * 256 + n]);
    }
    if (idx < GD * NN * DIMM) {      // init H + C
        int j  = idx & (DIMM - 1);
        int gd = idx / (NN * DIMM);
        int r  = idx % (NN * DIMM);
        g_Hf16[0][gd][r] = __float2half(ih[gd * DIMM + j]);
        g_C[gd][r] = ic[gd * DIMM + j];
    }
}

// ---- HMMA recurrent steps, ALL 16 FUSED: CTA 128x128, 8 warps, 2 CTAs/SM ----
// bid = t*2048 + mtile*64 + gd*8 + ntile  (t ascending => producers have smaller bid)
// Flag wait deferred to c==2 (chunks 0-3 are child gathers, independent of H(t-1)).
#define SSPA      18432                    // A: 128 rows x 144B
#define SSPB      18432                    // B: 128 rows x 144B
#define SBUF      (SSPA + SSPB)            // 36864
#define SSM_CHILD (3 * SBUF)               // 110592
#define SMEM_STEPK (3 * SBUF + 512)        // 111104

__global__ __launch_bounds__(256, 2) void step_mma_kernel(
    const int* __restrict__ indice, const float* __restrict__ lb) {
    extern __shared__ __align__(1024) char smem[];
    const int bid   = blockIdx.x;
    const int t     = bid >> 11;
    const int rem   = bid & 2047;
    const int mtile = rem >> 6;
    const int gd    = (rem >> 3) & 7;
    const int ntile = rem & 7;               // 128 packed cols = 32 dims
    const int Mact  = g_cnt[t];
    const int m0    = mtile * 128;
    if (m0 >= Mact) return;
    const int tid = threadIdx.x;
    const int wid = tid >> 5, lane = tid & 31;
    const uint32_t sb = smem_u32(smem);
    int* childs = (int*)(smem + SSM_CHILD);

    if (tid < 128) {
        int s = m0 + tid;
        int ci = 0;
        if (s < Mact) {
            int orig = g_sorted_orig[s];
            int len  = g_sorted_len[s];
            int tt = (gd & 1) ? (len - 1 - t) : t;
            ci = indice[orig * KK + tt];
        }
        childs[tid] = ci;
    }
    __syncthreads();

    const __half* Hin = &g_Hf16[t & 1][gd][0];
    const size_t bblk = (size_t)(gd * 8 + ntile) * 8;

    float acc[2][8][4];                      // warp tile 32x64: [mt2][nf8][quad]
#pragma unroll
    for (int mt = 0; mt < 2; mt++)
#pragma unroll
        for (int nf = 0; nf < 8; nf++)
#pragma unroll
            for (int u = 0; u < 4; u++) acc[mt][nf][u] = 0.f;

    const int mw = wid & 3, nw = wid >> 2;   // 4 x 2 warp grid
    const int m0w = mw * 32, n0w = nw * 64;
    const int am = lane >> 3, ar = lane & 7;

    auto stage = [&](int c) {
        uint32_t base = sb + (c % 3) * SBUF;
        uint32_t aS = base;
        uint32_t bS = base + SSPA;
#pragma unroll
        for (int i = 0; i < 4; i++) {       // A: 1024 segs of 16B
            int g = tid + i * 256;
            int row = g >> 3, seg = g & 7;
            const __half* src;
            if (c < 4) src = g_hf16 + (size_t)childs[row] * 256 + c * 64 + seg * 8;
            else       src = Hin + (size_t)(m0 + row) * 256 + (c - 4) * 64 + seg * 8;
            CP_ASYNC16(aS + row * 144 + seg * 16, src);
        }
        const __half* bw = g_Bpf + (bblk + c) * 8192u;
#pragma unroll
        for (int i = 0; i < 4; i++) {       // B: 1024 segs of 16B
            int g = tid + i * 256;
            int row = g >> 3, seg = g & 7;
            CP_ASYNC16(bS + row * 144 + seg * 16, bw + row * 64 + seg * 8);
        }
        CP_COMMIT();
    };

    auto compute = [&](int c) {
        uint32_t base = sb + (c % 3) * SBUF;
        uint32_t aS = base;
        uint32_t bS = base + SSPA;
#pragma unroll
        for (int ks = 0; ks < 4; ks++) {
            int k0 = ks * 16;
            uint32_t af[2][4];
            int arow_off = ((am & 1) ? 8 : 0) + ar;
            int akk = (k0 + ((am >= 2) ? 8 : 0)) * 2;
#pragma unroll
            for (int mt = 0; mt < 2; mt++) {
                uint32_t off = (uint32_t)(m0w + mt * 16 + arow_off) * 144 + akk;
                ldsm4(af[mt], aS + off);
            }
            int brow_off = ((am >= 2) ? 8 : 0) + ar;
            int bkk = (k0 + ((am & 1) ? 8 : 0)) * 2;
#pragma unroll
            for (int np = 0; np < 4; np++) {
                uint32_t off = (uint32_t)(n0w + np * 16 + brow_off) * 144 + bkk;
                uint32_t rb[4];
                ldsm4(rb, bS + off);
                uint32_t b0[2] = {rb[0], rb[1]}, b1[2] = {rb[2], rb[3]};
#pragma unroll
                for (int mt = 0; mt < 2; mt++) {
                    mma_f16(acc[mt][np * 2], af[mt], b0);
                    mma_f16(acc[mt][np * 2 + 1], af[mt], b1);
                }
            }
        }
    };

    stage(0);
    stage(1);
#pragma unroll
    for (int c = 0; c < 8; c++) {
        if (c == 7) { CP_WAIT(0); } else { CP_WAIT(1); }
        __syncthreads();
        if (c == 2 && t > 0) {              // H(t-1) dependency gates staging chunk 4
            if (tid == 0) {
                const int* flag = &g_done[(((t - 1) * 8 + gd) << 5) + mtile];
                int v;
                do {
                    asm volatile("ld.acquire.gpu.global.s32 %0, [%1];" : "=r"(v) : "l"(flag));
                } while (v < 8);
            }
            __syncthreads();
        }
        if (c + 2 < 8) stage(c + 2);
        compute(c);
    }
    __syncthreads();

    // epilogue: accums -> smem (stride 132), then pointwise LSTM
    float* zs = (float*)smem;    // [128][132]
#pragma unroll
    for (int mt = 0; mt < 2; mt++)
#pragma unroll
        for (int nf = 0; nf < 8; nf++) {
            int row = m0w + mt * 16 + (lane >> 2);
            int col = n0w + nf * 8 + (lane & 3) * 2;
            zs[row * 132 + col]           = acc[mt][nf][0];
            zs[row * 132 + col + 1]       = acc[mt][nf][1];
            zs[(row + 8) * 132 + col]     = acc[mt][nf][2];
            zs[(row + 8) * 132 + col + 1] = acc[mt][nf][3];
        }
    __syncthreads();

    const int dsel = gd & 1;
    const bool isG0 = gd < 2;
    const int par = (t + 1) & 1;
    const int cntNext = (t < 15) ? g_cnt[t + 1] : 0;   // rows with len == t+1: s >= cntNext
#pragma unroll
    for (int i = 0; i < 16; i++) {
        int e = tid + i * 256;              // 128 rows x 32 dims
        int row = e >> 5, d = e & 31;
        int s = m0 + row;
        if (s < Mact) {
            int jb = ntile * 32 + d;
            float zi = zs[row * 132 + 4 * d + 0] + lb[gd * 1024 + jb];
            float zf = zs[row * 132 + 4 * d + 1] + lb[gd * 1024 + 256 + jb];
            float zu = zs[row * 132 + 4 * d + 2] + lb[gd * 1024 + 512 + jb];
            float zo = zs[row * 132 + 4 * d + 3] + lb[gd * 1024 + 768 + jb];
            size_t off = (size_t)s * DIMM + jb;
            float cnew = sigm(zf) * g_C[gd][off] + sigm(zi) * tanh_fast(zu);
            float hnew = sigm(zo) * tanh_fast(cnew);
            g_C[gd][off] = cnew;
            __half hh = __float2half(hnew);
            g_Hf16[par][gd][off] = hh;
            if (isG0) g_Yf16[dsel][((size_t)t * NN + s) * DIMM + jb] = hh;  // (t*NN+s) layout
            if (s >= cntNext) g_Hfin[gd][off] = hh;    // t == len-1: final h
        }
    }

    // signal completion of (t, gd, mtile, ntile)
    __threadfence();
    __syncthreads();
    if (tid == 0) atomicAdd(&g_done[((t * 8 + gd) << 5) + mtile], 1);
}

// ---- generic HMMA fc GEMM: C[M,256] = [A0|A1][M,512] @ Bp^T, 16 warps, 32x64 ----
#define SPA       18432                    // 128 rows x 144B
#define SPB       36864                    // 256 rows x 144B
#define BUF_B     (SPA + SPB)              // 55296
#define SMEM_FC   (3 * BUF_B + 512)        // 166400
#define NT        512

// mode 0: f_seq, grid (32, 16): y = t segment, prefix-trimmed by g_cnt[t].
// mode 9: y_last gates, grid (32, 3): gate = 1 + blockIdx.y
__global__ __launch_bounds__(NT, 1) void gemm_fc_kernel(int mode) {
    extern __shared__ __align__(1024) char smem[];
    const int tid = threadIdx.x;
    const int wid = tid >> 5, lane = tid & 31;
    const uint32_t sb = smem_u32(smem);

    int md = mode;
    if (md == 9) md = 1 + blockIdx.y;

    const __half *A0, *A1, *Bp;
    float* Cout;
    size_t rbase;                       // global row base for this CTA
    if (md == 0) {
        int tseg = blockIdx.y;
        int m0 = blockIdx.x * 128;
        if (m0 >= g_cnt[tseg]) return;  // prefix trim: only valid (t,s) rows
        rbase = (size_t)tseg * NN + m0;
        A0 = g_Yf16[0]; A1 = g_Yf16[1];
        Bp = g_fcp; Cout = g_fseq;
    } else {
        rbase = (size_t)blockIdx.x * 128;
        A0 = g_Hfin[2 * md]; A1 = g_Hfin[2 * md + 1];
        Bp = g_fcp + (size_t)md * 131072u;
        Cout = g_ydot + (size_t)(md - 1) * NN * DIMM;
    }

    float acc[2][8][4];
#pragma unroll
    for (int mt = 0; mt < 2; mt++)
#pragma unroll
        for (int nf = 0; nf < 8; nf++)
#pragma unroll
            for (int u = 0; u < 4; u++) acc[mt][nf][u] = 0.f;

    const int mw = wid & 3, nw = wid >> 2;
    const int m0w = mw * 32, n0w = nw * 64;
    const int am = lane >> 3, ar = lane & 7;

    auto stage = [&](int c) {
        uint32_t base = sb + (c % 3) * BUF_B;
        uint32_t aS = base;
        uint32_t bS = base + SPA;
#pragma unroll
        for (int i = 0; i < 2; i++) {
            int g = tid + i * NT;
            int row = g >> 3, seg = g & 7;
            const __half* src = (c < 4)
                ? A0 + (rbase + row) * 256 + c * 64 + seg * 8
                : A1 + (rbase + row) * 256 + (c - 4) * 64 + seg * 8;
            CP_ASYNC16(aS + row * 144 + seg * 16, src);
        }
#pragma unroll
        for (int i = 0; i < 4; i++) {
            int g = tid + i * NT;
            int row = g >> 3, seg = g & 7;   // row = n index, Bp stride 512
            CP_ASYNC16(bS + row * 144 + seg * 16, Bp + (size_t)row * 512 + c * 64 + seg * 8);
        }
        CP_COMMIT();
    };

    auto compute = [&](int c) {
        uint32_t base = sb + (c % 3) * BUF_B;
        uint32_t aS = base;
        uint32_t bS = base + SPA;
#pragma unroll
        for (int ks = 0; ks < 4; ks++) {
            int k0 = ks * 16;
            uint32_t af[2][4];
            int arow_off = ((am & 1) ? 8 : 0) + ar;
            int akk = (k0 + ((am >= 2) ? 8 : 0)) * 2;
#pragma unroll
            for (int mt = 0; mt < 2; mt++) {
                uint32_t off = (uint32_t)(m0w + mt * 16 + arow_off) * 144 + akk;
                ldsm4(af[mt], aS + off);
            }
            int brow_off = ((am >= 2) ? 8 : 0) + ar;
            int bkk = (k0 + ((am & 1) ? 8 : 0)) * 2;
#pragma unroll
            for (int np = 0; np < 4; np++) {
                uint32_t off = (uint32_t)(n0w + np * 16 + brow_off) * 144 + bkk;
                uint32_t rb[4];
                ldsm4(rb, bS + off);
                uint32_t b0[2] = {rb[0], rb[1]}, b1[2] = {rb[2], rb[3]};
#pragma unroll
                for (int mt = 0; mt < 2; mt++) {
                    mma_f16(acc[mt][np * 2], af[mt], b0);
                    mma_f16(acc[mt][np * 2 + 1], af[mt], b1);
                }
            }
        }
    };

    stage(0);
    stage(1);
#pragma unroll
    for (int c = 0; c < 8; c++) {
        if (c == 7) { CP_WAIT(0); } else { CP_WAIT(1); }
        __syncthreads();
        if (c + 2 < 8) stage(c + 2);
        compute(c);
    }
    __syncthreads();

    float* zs = (float*)smem;    // [128][264]
#pragma unroll
    for (int mt = 0; mt < 2; mt++)
#pragma unroll
        for (int nf = 0; nf < 8; nf++) {
            int row = m0w + mt * 16 + (lane >> 2);
            int col = n0w + nf * 8 + (lane & 3) * 2;
            zs[row * 264 + col]           = acc[mt][nf][0];
            zs[row * 264 + col + 1]       = acc[mt][nf][1];
            zs[(row + 8) * 264 + col]     = acc[mt][nf][2];
            zs[(row + 8) * 264 + col + 1] = acc[mt][nf][3];
        }
    __syncthreads();

#pragma unroll
    for (int i = 0; i < 16; i++) {          // 128 rows x 64 float4s
        int e = tid + i * NT;
        int row = e >> 6, q = e & 63;
        float4 v = make_float4(zs[row * 264 + q * 4], zs[row * 264 + q * 4 + 1],
                               zs[row * 264 + q * 4 + 2], zs[row * 264 + q * 4 + 3]);
        *(float4*)&Cout[(rbase + row) * 256 + q * 4] = v;
    }
}

// ---- Wx HMMA GEMM: Wx[4096,1024] = x_f16 @ W_w^T + W_b ; grid (32, 4), K=256 ----
__global__ __launch_bounds__(NT, 1) void wx_mma_kernel(const float* __restrict__ W_b) {
    extern __shared__ __align__(1024) char smem[];
    const int tid = threadIdx.x;
    const int wid = tid >> 5, lane = tid & 31;
    const uint32_t sb = smem_u32(smem);
    const int m0 = blockIdx.x * 128;
    const int nt = blockIdx.y;              // col tile of 256

    float acc[2][8][4];
#pragma unroll
    for (int mt = 0; mt < 2; mt++)
#pragma unroll
        for (int nf = 0; nf < 8; nf++)
#pragma unroll
            for (int u = 0; u < 4; u++) acc[mt][nf][u] = 0.f;

    const int mw = wid & 3, nw = wid >> 2;
    const int m0w = mw * 32, n0w = nw * 64;
    const int am = lane >> 3, ar = lane & 7;

    auto stage = [&](int c) {
        uint32_t base = sb + (c % 3) * BUF_B;
        uint32_t aS = base;
        uint32_t bS = base + SPA;
#pragma unroll
        for (int i = 0; i < 2; i++) {
            int g = tid + i * NT;
            int row = g >> 3, seg = g & 7;
            CP_ASYNC16(aS + row * 144 + seg * 16,
                       g_xf16 + (size_t)(m0 + row) * 256 + c * 64 + seg * 8);
        }
        const __half* bw = g_wwp + (size_t)(nt * 4 + c) * 16384u;
#pragma unroll
        for (int i = 0; i < 4; i++) {
            int g = tid + i * NT;
            int row = g >> 3, seg = g & 7;
            CP_ASYNC16(bS + row * 144 + seg * 16, bw + (size_t)row * 64 + seg * 8);
        }
        CP_COMMIT();
    };

    auto compute = [&](int c) {
        uint32_t base = sb + (c % 3) * BUF_B;
        uint32_t aS = base;
        uint32_t bS = base + SPA;
#pragma unroll
        for (int ks = 0; ks < 4; ks++) {
            int k0 = ks * 16;
            uint32_t af[2][4];
            int arow_off = ((am & 1) ? 8 : 0) + ar;
            int akk = (k0 + ((am >= 2) ? 8 : 0)) * 2;
#pragma unroll
            for (int mt = 0; mt < 2; mt++) {
                uint32_t off = (uint32_t)(m0w + mt * 16 + arow_off) * 144 + akk;
                ldsm4(af[mt], aS + off);
            }
            int brow_off = ((am >= 2) ? 8 : 0) + ar;
            int bkk = (k0 + ((am & 1) ? 8 : 0)) * 2;
#pragma unroll
            for (int np = 0; np < 4; np++) {
                uint32_t off = (uint32_t)(n0w + np * 16 + brow_off) * 144 + bkk;
                uint32_t rb[4];
                ldsm4(rb, bS + off);
                uint32_t b0[2] = {rb[0], rb[1]}, b1[2] = {rb[2], rb[3]};
#pragma unroll
                for (int mt = 0; mt < 2; mt++) {
                    mma_f16(acc[mt][np * 2], af[mt], b0);
                    mma_f16(acc[mt][np * 2 + 1], af[mt], b1);
                }
            }
        }
    };

    stage(0);
    stage(1);
#pragma unroll
    for (int c = 0; c < 4; c++) {
        if (c == 3) { CP_WAIT(0); } else { CP_WAIT(1); }
        __syncthreads();
        if (c + 2 < 4) stage(c + 2);
        compute(c);
    }
    __syncthreads();

    float* zs = (float*)smem;    // [128][264]
#pragma unroll
    for (int mt = 0; mt < 2; mt++)
#pragma unroll
        for (int nf = 0; nf < 8; nf++) {
            int row = m0w + mt * 16 + (lane >> 2);
            int col = n0w + nf * 8 + (lane & 3) * 2;
            zs[row * 264 + col]           = acc[mt][nf][0];
            zs[row * 264 + col + 1]       = acc[mt][nf][1];
            zs[(row + 8) * 264 + col]     = acc[mt][nf][2];
            zs[(row + 8) * 264 + col + 1] = acc[mt][nf][3];
        }
    __syncthreads();

#pragma unroll
    for (int i = 0; i < 16; i++) {          // 128 rows x 64 float4s
        int e = tid + i * NT;
        int row = e >> 6, q = e & 63;
        float4 b = *(const float4*)&W_b[nt * 256 + q * 4];
        float4 v = make_float4(zs[row * 264 + q * 4] + b.x, zs[row * 264 + q * 4 + 1] + b.y,
                               zs[row * 264 + q * 4 + 2] + b.z, zs[row * 264 + q * 4 + 3] + b.w);
        *(float4*)&g_Wx[(size_t)(m0 + row) * 1024 + nt * 256 + q * 4] = v;
    }
}

// ---------------- final combine (light) ----------------
__global__ __launch_bounds__(256) void combine_kernel(
    const float* __restrict__ c_tensor, const int* __restrict__ indice,
    float* __restrict__ out) {
    int s = blockIdx.x;
    int j = threadIdx.x;
    int orig = g_sorted_orig[s];
    int len  = g_sorted_len[s];

    __shared__ int ciS[KK];
    if (j < KK) ciS[j] = (j < len) ? indice[orig * KK + j] : 0;
    __syncthreads();

    float Wf = g_Wx[orig * 1024 + j];
    float bf = 0.f;
    for (int t = 0; t < len; t++) {
        float fs = g_fseq[((size_t)t * NN + s) * DIMM + j];
        bf += sigm(Wf + fs) * c_tensor[(size_t)ciS[t] * DIMM + j];
    }

    float d0 = g_ydot[(size_t)0 * NN * DIMM + (size_t)s * DIMM + j];
    float d1 = g_ydot[(size_t)1 * NN * DIMM + (size_t)s * DIMM + j];
    float d2 = g_ydot[(size_t)2 * NN * DIMM + (size_t)s * DIMM + j];

    float Wi = g_Wx[orig * 1024 + 256 + j];
    float Wu = g_Wx[orig * 1024 + 512 + j];
    float Wo = g_Wx[orig * 1024 + 768 + j];
    float bi = sigm(d0 + Wi);
    float bu = tanh_fast(d1 + Wu);
    float bo = sigm(d2 + Wo);
    float nc = bi * bu + bf;
    float nh = bo * tanh_fast(nc);
    out[(size_t)orig * DIMM + j] = nh;
    out[(size_t)NN * DIMM + (size_t)orig * DIMM + j] = nc;
}

// ---------------- launch ----------------
extern "C" void kernel_launch(void* const* d_in, const int* in_sizes, int n_in,
                              void* d_out, int out_size) {
    const float* x        = (const float*)d_in[0];
    const float* h_tensor = (const float*)d_in[1];
    const float* c_tensor = (const float*)d_in[2];
    const int*   indice   = (const int*)d_in[3];
    const float* W_w      = (const float*)d_in[4];
    const float* W_b      = (const float*)d_in[5];
    const float* lk       = (const float*)d_in[6];
    const float* lr       = (const float*)d_in[7];
    const float* lb       = (const float*)d_in[8];
    const float* ih       = (const float*)d_in[9];
    const float* ic       = (const float*)d_in[10];
    const float* fc       = (const float*)d_in[11];
    float* out = (float*)d_out;

    cudaFuncSetAttribute(step_mma_kernel, cudaFuncAttributeMaxDynamicSharedMemorySize,
                         SMEM_STEPK);
    cudaFuncSetAttribute(gemm_fc_kernel, cudaFuncAttributeMaxDynamicSharedMemorySize,
                         SMEM_FC);
    cudaFuncSetAttribute(wx_mma_kernel, cudaFuncAttributeMaxDynamicSharedMemorySize,
                         SMEM_FC);

    zero_hist_kernel<<<1, 32>>>();
    len_hist_kernel<<<NN / 256, 256>>>(indice);
    prefix_kernel<<<1, 1>>>();
    scatter_kernel<<<NN / 256, 256>>>(indice);
    prep_kernel<<<(GD * NN * DIMM) / 256, 256>>>(ih, ic, lk, lr, h_tensor, fc, x, W_w);
    step_mma_kernel<<<16 * 2048, 256, SMEM_STEPK>>>(indice, lb);   // all 16 steps, fused
    gemm_fc_kernel<<<dim3(32, 16), NT, SMEM_FC>>>(0);             // f_seq (prefix-trimmed)
    gemm_fc_kernel<<<dim3(32, 3), NT, SMEM_FC>>>(9);              // y_last gates 1..3
    wx_mma_kernel<<<dim3(32, 4), NT, SMEM_FC>>>(W_b);             // Wx (fp16 HMMA)
    combine_kernel<<<NN, 256>>>(c_tensor, indice, out);
}

// round 16
// speedup vs baseline: 1.2047x; 1.0194x over previous
#include <cuda_runtime.h>
#include <cuda_fp16.h>
#include <math.h>
#include <cstdint>

#define NN   4096
#define KK   16
#define DIMM 256
#define RR   8192
#define GD   8

// ---- device scratch (static, no allocation) ----
__device__ int   g_hist[17];
__device__ int   g_off[17];
__device__ int   g_cnt[16];
__device__ int   g_done[16 * 8 * 32];          // [t][gd][mtile] ntile-completion counters
__device__ int   g_sorted_orig[NN];
__device__ int   g_sorted_len[NN];
__device__ float g_Wx[NN * 1024];
__device__ float g_C[GD][NN * DIMM];           // c state fp32
__device__ __half g_Yf16[2][NN * KK * DIMM];   // gate-0 seq outputs, layout (t*NN+s)
__device__ __half g_Hfin[GD][NN * DIMM];       // final h per gd (fp16)
__device__ float g_fseq[NN * KK * DIMM];       // fc0 projection, layout (t*NN+s)
__device__ float g_ydot[3 * NN * DIMM];        // fc1..3 projections of y_last
// fp16 h/H state + weights
__device__ __half g_hf16[RR * DIMM];            // h_tensor (rounded)
__device__ __half g_Hf16[2][GD][NN * DIMM];     // H state (double buffered)
__device__ __half g_xf16[NN * DIMM];            // x (rounded)
// packed weights: [gd][ntile8][chunk8] blocks of 128 n-rows x 64 k halves (K-major BT)
__device__ __half g_Bpf[8u * 8u * 8u * 8192u];
// packed fc weights: [gate4][256 n][512 k] fp16 (BT, K-major)
__device__ __half g_fcp[4u * 256u * 512u];
// packed W_w BT: [1024 n][256 k]
__device__ __half g_wwp2[1024u * 256u];

// ---- fast approx math (ex2/rcp approx, ~2^-22 error) ----
__device__ __forceinline__ float ex2f(float x) {
    float r; asm("ex2.approx.f32 %0, %1;" : "=f"(r) : "f"(x)); return r;
}
__device__ __forceinline__ float rcpf(float x) {
    float r; asm("rcp.approx.f32 %0, %1;" : "=f"(r) : "f"(x)); return r;
}
__device__ __forceinline__ float sigm(float x) {
    return rcpf(1.f + ex2f(-1.4426950408889634f * x));
}
__device__ __forceinline__ float tanh_fast(float x) {
    return 1.f - 2.f * rcpf(1.f + ex2f(2.8853900817779268f * x));
}

// ---- PTX helpers (non-'a' features only: cp.async, ldmatrix, mma.sync) ----
__device__ __forceinline__ uint32_t smem_u32(const void* p) {
    uint32_t a;
    asm("{ .reg .u64 t; cvta.to.shared.u64 t, %1; cvt.u32.u64 %0, t; }" : "=r"(a) : "l"(p));
    return a;
}
#define CP_ASYNC16(dst, src) \
    asm volatile("cp.async.cg.shared.global [%0], [%1], 16;" :: "r"(dst), "l"(src))
#define CP_COMMIT() asm volatile("cp.async.commit_group;" ::: "memory")
#define CP_WAIT(n)  asm volatile("cp.async.wait_group %0;" :: "n"(n) : "memory")

__device__ __forceinline__ void ldsm4(uint32_t* r, uint32_t addr) {
    asm volatile("ldmatrix.sync.aligned.m8n8.x4.shared.b16 {%0,%1,%2,%3}, [%4];"
                 : "=r"(r[0]), "=r"(r[1]), "=r"(r[2]), "=r"(r[3]) : "r"(addr));
}
__device__ __forceinline__ void mma_f16(float* c, const uint32_t* a, const uint32_t* b) {
    asm volatile("mma.sync.aligned.m16n8k16.row.col.f32.f16.f16.f32 "
                 "{%0,%1,%2,%3}, {%4,%5,%6,%7}, {%8,%9}, {%0,%1,%2,%3};"
                 : "+f"(c[0]), "+f"(c[1]), "+f"(c[2]), "+f"(c[3])
                 : "r"(a[0]), "r"(a[1]), "r"(a[2]), "r"(a[3]), "r"(b[0]), "r"(b[1]));
}

// ---------------- sorting by length (desc) ----------------
__global__ void zero_hist_kernel() { if (threadIdx.x < 17) g_hist[threadIdx.x] = 0; }

__global__ void len_hist_kernel(const int* __restrict__ indice) {
    int n = blockIdx.x * blockDim.x + threadIdx.x;
    if (n >= NN) return;
    int len = 0;
#pragma unroll
    for (int k = 0; k < KK; k++) len += (indice[n * KK + k] != -1);
    atomicAdd(&g_hist[len], 1);
}

__global__ void prefix_kernel() {
    if (threadIdx.x != 0 || blockIdx.x != 0) return;
    int run = 0;
    for (int l = 16; l >= 1; l--) { g_off[l] = run; run += g_hist[l]; }
    for (int t = 0; t < 16; t++) g_cnt[t] = g_off[t + 1] + g_hist[t + 1];
}

__global__ void scatter_kernel(const int* __restrict__ indice) {
    int n = blockIdx.x * blockDim.x + threadIdx.x;
    if (n >= NN) return;
    int len = 0;
#pragma unroll
    for (int k = 0; k < KK; k++) len += (indice[n * KK + k] != -1);
    int pos = atomicAdd(&g_off[len], 1);
    g_sorted_orig[pos] = n;
    g_sorted_len[pos]  = len;
}

// ------- prep: round h/x, pack weights (lstm + fc + wx), init states, zero flags -------
__global__ void prep_kernel(const float* __restrict__ ih, const float* __restrict__ ic,
                            const float* __restrict__ lk, const float* __restrict__ lr,
                            const float* __restrict__ h_tensor,
                            const float* __restrict__ fc_w,
                            const float* __restrict__ x, const float* __restrict__ W_w) {
    int idx = blockIdx.x * blockDim.x + threadIdx.x;
    if (idx < 16 * 8 * 32) {         // zero step-dependency flags (every call: graph replay)
        g_done[idx] = 0;
    }
    if (idx < RR * DIMM) {           // h_tensor round
        g_hf16[idx] = __float2half(h_tensor[idx]);
    }
    if (idx < NN * DIMM) {           // x round
        g_xf16[idx] = __float2half(x[idx]);
    }
    if (idx < 8 * 512 * 1024) {      // lstm weight pack: gate-interleaved, K-major BT blocks
        int gd = idx >> 19;
        int rem = idx & ((1 << 19) - 1);
        int kg = rem >> 10;          // 0..511
        int pc = rem & 1023;         // packed col: 4*j + q (q: 0=i,1=f,2=u,3=o)
        int oc = (pc & 3) * 256 + (pc >> 2);
        float w = (kg < 256) ? lk[((size_t)gd * 256 + kg) * 1024 + oc]
                             : lr[((size_t)gd * 256 + (kg - 256)) * 1024 + oc];
        int ntile = pc >> 7;         // 8 tiles of 128 packed cols
        int n     = pc & 127;
        int chunk = kg >> 6;
        int k     = kg & 63;
        size_t dst = ((size_t)(gd * 8 + ntile) * 8 + chunk) * 8192u + (size_t)n * 64 + k;
        g_Bpf[dst] = __float2half(w);
    }
    if (idx < 4 * 256 * 512) {       // fc weight pack: BT [gate][n][k]
        int g = idx >> 17;
        int rem = idx & ((1 << 17) - 1);
        int n = rem >> 9, k = rem & 511;
        g_fcp[idx] = __float2half(fc_w[((size_t)g * 512 + k) * 256 + n]);
    }
    if (idx < 1024 * 256) {          // W_w pack: BT [n1024][k256]
        int oc = idx >> 8, k = idx & 255;
        g_wwp2[idx] = __float2half(W_w[(size_t)k * 1024 + oc]);
    }
    if (idx < GD * NN * DIMM) {      // init H + C
        int j  = idx & (DIMM - 1);
        int gd = idx / (NN * DIMM);
        int r  = idx % (NN * DIMM);
        g_Hf16[0][gd][r] = __float2half(ih[gd * DIMM + j]);
        g_C[gd][r] = ic[gd * DIMM + j];
    }
}

// ---- MEGA kernel: 16 fused LSTM steps + fc/wx GEMMs, all one grid ----
// bids [0, 32768): step   t*2048 + mtile*64 + gd*8 + ntile
// bids [32768, 33792): f_seq   (tseg, mtile, nt01)   flags: gd 0,1 @ tseg
// bids [33792, 33984): gates   (gate 1..3, mtile, nt01)  flags: gd 2g,2g+1 @ len(m0)-1
// bids [33984, 34240): wx      (mtile, nt8)               no flags
#define SSPA      18432                    // A: 128 rows x 144B
#define SSPB      18432                    // B: 128 rows x 144B
#define SBUF      (SSPA + SSPB)            // 36864
#define SSM_CHILD (3 * SBUF)               // 110592
#define SMEM_STEPK (3 * SBUF + 512)        // 111104

__global__ __launch_bounds__(256, 2) void mega_kernel(
    const int* __restrict__ indice, const float* __restrict__ lb,
    const float* __restrict__ W_b) {
    extern __shared__ __align__(1024) char smem[];
    const int bid = blockIdx.x;
    const int tid = threadIdx.x;
    const int wid = tid >> 5, lane = tid & 31;
    const uint32_t sb = smem_u32(smem);
    const int mw = wid & 3, nw = wid >> 2;   // 4 x 2 warp grid, warp 32x64
    const int m0w = mw * 32, n0w = nw * 64;
    const int am = lane >> 3, ar = lane & 7;

    if (bid < 32768) {
        // ================= STEP PATH =================
        const int t     = bid >> 11;
        const int rem   = bid & 2047;
        const int mtile = rem >> 6;
        const int gd    = (rem >> 3) & 7;
        const int ntile = rem & 7;
        const int Mact  = g_cnt[t];
        const int m0    = mtile * 128;
        if (m0 >= Mact) return;
        int* childs = (int*)(smem + SSM_CHILD);

        if (tid < 128) {
            int s = m0 + tid;
            int ci = 0;
            if (s < Mact) {
                int orig = g_sorted_orig[s];
                int len  = g_sorted_len[s];
                int tt = (gd & 1) ? (len - 1 - t) : t;
                ci = indice[orig * KK + tt];
            }
            childs[tid] = ci;
        }
        __syncthreads();

        const __half* Hin = &g_Hf16[t & 1][gd][0];
        const size_t bblk = (size_t)(gd * 8 + ntile) * 8;

        float acc[2][8][4];
#pragma unroll
        for (int mt = 0; mt < 2; mt++)
#pragma unroll
            for (int nf = 0; nf < 8; nf++)
#pragma unroll
                for (int u = 0; u < 4; u++) acc[mt][nf][u] = 0.f;

        auto stage = [&](int c) {
            uint32_t aS = sb + (c % 3) * SBUF;
            uint32_t bS = aS + SSPA;
#pragma unroll
            for (int i = 0; i < 4; i++) {
                int g = tid + i * 256;
                int row = g >> 3, seg = g & 7;
                const __half* src;
                if (c < 4) src = g_hf16 + (size_t)childs[row] * 256 + c * 64 + seg * 8;
                else       src = Hin + (size_t)(m0 + row) * 256 + (c - 4) * 64 + seg * 8;
                CP_ASYNC16(aS + row * 144 + seg * 16, src);
            }
            const __half* bw = g_Bpf + (bblk + c) * 8192u;
#pragma unroll
            for (int i = 0; i < 4; i++) {
                int g = tid + i * 256;
                int row = g >> 3, seg = g & 7;
                CP_ASYNC16(bS + row * 144 + seg * 16, bw + row * 64 + seg * 8);
            }
            CP_COMMIT();
        };
        auto compute = [&](int c) {
            uint32_t aS = sb + (c % 3) * SBUF;
            uint32_t bS = aS + SSPA;
#pragma unroll
            for (int ks = 0; ks < 4; ks++) {
                int k0 = ks * 16;
                uint32_t af[2][4];
                int arow_off = ((am & 1) ? 8 : 0) + ar;
                int akk = (k0 + ((am >= 2) ? 8 : 0)) * 2;
#pragma unroll
                for (int mt = 0; mt < 2; mt++) {
                    uint32_t off = (uint32_t)(m0w + mt * 16 + arow_off) * 144 + akk;
                    ldsm4(af[mt], aS + off);
                }
                int brow_off = ((am >= 2) ? 8 : 0) + ar;
                int bkk = (k0 + ((am & 1) ? 8 : 0)) * 2;
#pragma unroll
                for (int np = 0; np < 4; np++) {
                    uint32_t off = (uint32_t)(n0w + np * 16 + brow_off) * 144 + bkk;
                    uint32_t rb[4];
                    ldsm4(rb, bS + off);
                    uint32_t b0[2] = {rb[0], rb[1]}, b1[2] = {rb[2], rb[3]};
#pragma unroll
                    for (int mt = 0; mt < 2; mt++) {
                        mma_f16(acc[mt][np * 2], af[mt], b0);
                        mma_f16(acc[mt][np * 2 + 1], af[mt], b1);
                    }
                }
            }
        };

        stage(0);
        stage(1);
#pragma unroll
        for (int c = 0; c < 8; c++) {
            if (c == 7) { CP_WAIT(0); } else { CP_WAIT(1); }
            __syncthreads();
            if (c == 2 && t > 0) {
                if (tid == 0) {
                    const int* flag = &g_done[(((t - 1) * 8 + gd) << 5) + mtile];
                    int v;
                    do {
                        asm volatile("ld.acquire.gpu.global.s32 %0, [%1];" : "=r"(v) : "l"(flag));
                    } while (v < 8);
                }
                __syncthreads();
            }
            if (c + 2 < 8) stage(c + 2);
            compute(c);
        }
        __syncthreads();

        float* zs = (float*)smem;    // [128][132]
#pragma unroll
        for (int mt = 0; mt < 2; mt++)
#pragma unroll
            for (int nf = 0; nf < 8; nf++) {
                int row = m0w + mt * 16 + (lane >> 2);
                int col = n0w + nf * 8 + (lane & 3) * 2;
                zs[row * 132 + col]           = acc[mt][nf][0];
                zs[row * 132 + col + 1]       = acc[mt][nf][1];
                zs[(row + 8) * 132 + col]     = acc[mt][nf][2];
                zs[(row + 8) * 132 + col + 1] = acc[mt][nf][3];
            }
        __syncthreads();

        const int dsel = gd & 1;
        const bool isG0 = gd < 2;
        const int par = (t + 1) & 1;
        const int cntNext = (t < 15) ? g_cnt[t + 1] : 0;
#pragma unroll
        for (int i = 0; i < 16; i++) {
            int e = tid + i * 256;
            int row = e >> 5, d = e & 31;
            int s = m0 + row;
            if (s < Mact) {
                int jb = ntile * 32 + d;
                float zi = zs[row * 132 + 4 * d + 0] + lb[gd * 1024 + jb];
                float zf = zs[row * 132 + 4 * d + 1] + lb[gd * 1024 + 256 + jb];
                float zu = zs[row * 132 + 4 * d + 2] + lb[gd * 1024 + 512 + jb];
                float zo = zs[row * 132 + 4 * d + 3] + lb[gd * 1024 + 768 + jb];
                size_t off = (size_t)s * DIMM + jb;
                float cnew = sigm(zf) * g_C[gd][off] + sigm(zi) * tanh_fast(zu);
                float hnew = sigm(zo) * tanh_fast(cnew);
                g_C[gd][off] = cnew;
                __half hh = __float2half(hnew);
                g_Hf16[par][gd][off] = hh;
                if (isG0) g_Yf16[dsel][((size_t)t * NN + s) * DIMM + jb] = hh;
                if (s >= cntNext) g_Hfin[gd][off] = hh;
            }
        }

        __threadfence();
        __syncthreads();
        if (tid == 0) atomicAdd(&g_done[((t * 8 + gd) << 5) + mtile], 1);
        return;
    }

    // ================= GENERIC GEMM PATH (f_seq / gates / wx) =================
    int q = bid - 32768;
    const __half *A0, *A1, *Bsrc;
    int Bstride, nch, cbase, cstride;
    float* Cout;
    const float* bias = nullptr;
    const int *flag0 = nullptr, *flag1 = nullptr;

    if (q < 1024) {                     // f_seq
        int tseg = q >> 6, r2 = q & 63, mt = r2 >> 1, nt01 = r2 & 1;
        int m0g = mt * 128;
        if (m0g >= g_cnt[tseg]) return;
        size_t rb = (size_t)tseg * NN + m0g;
        A0 = g_Yf16[0] + rb * 256;
        A1 = g_Yf16[1] + rb * 256;
        Bsrc = g_fcp + nt01 * 128 * 512;
        Bstride = 512; nch = 8;
        Cout = g_fseq + rb * 256; cstride = 256; cbase = nt01 * 128;
        flag0 = &g_done[((tseg * 8 + 0) << 5) + mt];
        flag1 = &g_done[((tseg * 8 + 1) << 5) + mt];
    } else if (q < 1216) {              // y_last gates 1..3
        int r = q - 1024;
        int g = 1 + (r >> 6);
        int r2 = r & 63, mt = r2 >> 1, nt01 = r2 & 1;
        int m0g = mt * 128;
        A0 = g_Hfin[2 * g] + (size_t)m0g * 256;
        A1 = g_Hfin[2 * g + 1] + (size_t)m0g * 256;
        Bsrc = g_fcp + (size_t)g * 131072u + nt01 * 128 * 512;
        Bstride = 512; nch = 8;
        Cout = g_ydot + (size_t)(g - 1) * NN * DIMM + (size_t)m0g * 256;
        cstride = 256; cbase = nt01 * 128;
        int tmax = g_sorted_len[m0g] - 1;
        flag0 = &g_done[((tmax * 8 + 2 * g) << 5) + mt];
        flag1 = &g_done[((tmax * 8 + 2 * g + 1) << 5) + mt];
    } else {                            // wx
        int r = q - 1216;
        int mt = r >> 3, nt = r & 7;
        int m0g = mt * 128;
        A0 = g_xf16 + (size_t)m0g * 256;
        A1 = A0;
        Bsrc = g_wwp2 + (size_t)nt * 128 * 256;
        Bstride = 256; nch = 4;
        Cout = g_Wx + (size_t)m0g * 1024; cstride = 1024; cbase = nt * 128;
        bias = W_b;
    }

    if (flag0) {
        if (tid == 0) {
            int v;
            do { asm volatile("ld.acquire.gpu.global.s32 %0, [%1];" : "=r"(v) : "l"(flag0)); } while (v < 8);
            do { asm volatile("ld.acquire.gpu.global.s32 %0, [%1];" : "=r"(v) : "l"(flag1)); } while (v < 8);
        }
        __syncthreads();
    }

    float acc[2][8][4];
#pragma unroll
    for (int mt = 0; mt < 2; mt++)
#pragma unroll
        for (int nf = 0; nf < 8; nf++)
#pragma unroll
            for (int u = 0; u < 4; u++) acc[mt][nf][u] = 0.f;

    auto stageG = [&](int c) {
        uint32_t aS = sb + (c % 3) * SBUF;
        uint32_t bS = aS + SSPA;
        const __half* Asel = (c < 4) ? A0 : A1;
        int coff = (c & 3) * 64;
#pragma unroll
        for (int i = 0; i < 4; i++) {
            int g = tid + i * 256;
            int row = g >> 3, seg = g & 7;
            CP_ASYNC16(aS + row * 144 + seg * 16, Asel + (size_t)row * 256 + coff + seg * 8);
        }
#pragma unroll
        for (int i = 0; i < 4; i++) {
            int g = tid + i * 256;
            int row = g >> 3, seg = g & 7;
            CP_ASYNC16(bS + row * 144 + seg * 16, Bsrc + (size_t)row * Bstride + c * 64 + seg * 8);
        }
        CP_COMMIT();
    };
    auto computeG = [&](int c) {
        uint32_t aS = sb + (c % 3) * SBUF;
        uint32_t bS = aS + SSPA;
#pragma unroll
        for (int ks = 0; ks < 4; ks++) {
            int k0 = ks * 16;
            uint32_t af[2][4];
            int arow_off = ((am & 1) ? 8 : 0) + ar;
            int akk = (k0 + ((am >= 2) ? 8 : 0)) * 2;
#pragma unroll
            for (int mt = 0; mt < 2; mt++) {
                uint32_t off = (uint32_t)(m0w + mt * 16 + arow_off) * 144 + akk;
                ldsm4(af[mt], aS + off);
            }
            int brow_off = ((am >= 2) ? 8 : 0) + ar;
            int bkk = (k0 + ((am & 1) ? 8 : 0)) * 2;
#pragma unroll
            for (int np = 0; np < 4; np++) {
                uint32_t off = (uint32_t)(n0w + np * 16 + brow_off) * 144 + bkk;
                uint32_t rb[4];
                ldsm4(rb, bS + off);
                uint32_t b0[2] = {rb[0], rb[1]}, b1[2] = {rb[2], rb[3]};
#pragma unroll
                for (int mt = 0; mt < 2; mt++) {
                    mma_f16(acc[mt][np * 2], af[mt], b0);
                    mma_f16(acc[mt][np * 2 + 1], af[mt], b1);
                }
            }
        }
    };

    stageG(0);
    stageG(1);
    for (int c = 0; c < nch; c++) {
        if (c == nch - 1) { CP_WAIT(0); } else { CP_WAIT(1); }
        __syncthreads();
        if (c + 2 < nch) stageG(c + 2);
        computeG(c);
    }
    __syncthreads();

    float* zs = (float*)smem;    // [128][132]
#pragma unroll
    for (int mt = 0; mt < 2; mt++)
#pragma unroll
        for (int nf = 0; nf < 8; nf++) {
            int row = m0w + mt * 16 + (lane >> 2);
            int col = n0w + nf * 8 + (lane & 3) * 2;
            zs[row * 132 + col]           = acc[mt][nf][0];
            zs[row * 132 + col + 1]       = acc[mt][nf][1];
            zs[(row + 8) * 132 + col]     = acc[mt][nf][2];
            zs[(row + 8) * 132 + col + 1] = acc[mt][nf][3];
        }
    __syncthreads();

#pragma unroll
    for (int i = 0; i < 16; i++) {      // 128 rows x 32 float4s
        int e = tid + i * 256;
        int row = e >> 5, q4 = e & 31;
        int col = q4 * 4;
        float4 v = make_float4(zs[row * 132 + col], zs[row * 132 + col + 1],
                               zs[row * 132 + col + 2], zs[row * 132 + col + 3]);
        if (bias) {
            float4 b = *(const float4*)&bias[cbase + col];
            v.x += b.x; v.y += b.y; v.z += b.z; v.w += b.w;
        }
        *(float4*)&Cout[(size_t)row * cstride + cbase + col] = v;
    }
}

// ---------------- final combine (light) ----------------
__global__ __launch_bounds__(256) void combine_kernel(
    const float* __restrict__ c_tensor, const int* __restrict__ indice,
    float* __restrict__ out) {
    int s = blockIdx.x;
    int j = threadIdx.x;
    int orig = g_sorted_orig[s];
    int len  = g_sorted_len[s];

    __shared__ int ciS[KK];
    if (j < KK) ciS[j] = (j < len) ? indice[orig * KK + j] : 0;
    __syncthreads();

    float Wf = g_Wx[orig * 1024 + j];
    float bf = 0.f;
    for (int t = 0; t < len; t++) {
        float fs = g_fseq[((size_t)t * NN + s) * DIMM + j];
        bf += sigm(Wf + fs) * c_tensor[(size_t)ciS[t] * DIMM + j];
    }

    float d0 = g_ydot[(size_t)0 * NN * DIMM + (size_t)s * DIMM + j];
    float d1 = g_ydot[(size_t)1 * NN * DIMM + (size_t)s * DIMM + j];
    float d2 = g_ydot[(size_t)2 * NN * DIMM + (size_t)s * DIMM + j];

    float Wi = g_Wx[orig * 1024 + 256 + j];
    float Wu = g_Wx[orig * 1024 + 512 + j];
    float Wo = g_Wx[orig * 1024 + 768 + j];
    float bi = sigm(d0 + Wi);
    float bu = tanh_fast(d1 + Wu);
    float bo = sigm(d2 + Wo);
    float nc = bi * bu + bf;
    float nh = bo * tanh_fast(nc);
    out[(size_t)orig * DIMM + j] = nh;
    out[(size_t)NN * DIMM + (size_t)orig * DIMM + j] = nc;
}

// ---------------- launch ----------------
extern "C" void kernel_launch(void* const* d_in, const int* in_sizes, int n_in,
                              void* d_out, int out_size) {
    const float* x        = (const float*)d_in[0];
    const float* h_tensor = (const float*)d_in[1];
    const float* c_tensor = (const float*)d_in[2];
    const int*   indice   = (const int*)d_in[3];
    const float* W_w      = (const float*)d_in[4];
    const float* W_b      = (const float*)d_in[5];
    const float* lk       = (const float*)d_in[6];
    const float* lr       = (const float*)d_in[7];
    const float* lb       = (const float*)d_in[8];
    const float* ih       = (const float*)d_in[9];
    const float* ic       = (const float*)d_in[10];
    const float* fc       = (const float*)d_in[11];
    float* out = (float*)d_out;

    cudaFuncSetAttribute(mega_kernel, cudaFuncAttributeMaxDynamicSharedMemorySize,
                         SMEM_STEPK);

    zero_hist_kernel<<<1, 32>>>();
    len_hist_kernel<<<NN / 256, 256>>>(indice);
    prefix_kernel<<<1, 1>>>();
    scatter_kernel<<<NN / 256, 256>>>(indice);
    prep_kernel<<<(GD * NN * DIMM) / 256, 256>>>(ih, ic, lk, lr, h_tensor, fc, x, W_w);
    mega_kernel<<<16 * 2048 + 1024 + 192 + 256, 256, SMEM_STEPK>>>(indice, lb, W_b);
    combine_kernel<<<NN, 256>>>(c_tensor, indice, out);
}